// round 1
// baseline (speedup 1.0000x reference)
#include <cuda_runtime.h>
#include <math.h>
#include <stdint.h>

// Problem constants
#define B_    4
#define S_    2048
#define D_    1024
#define H_    16
#define DK_   64
#define DOUT_ 1024
#define MROWS (B_ * S_)   // 8192

// Scratch (static __device__: no allocation allowed in kernel_launch)
__device__ float g_Q[(size_t)B_ * H_ * S_ * DK_];    // [B,H,S,DK]
__device__ float g_K[(size_t)B_ * H_ * S_ * DK_];
__device__ float g_V[(size_t)B_ * H_ * S_ * DK_];
__device__ float g_cat[(size_t)B_ * S_ * H_ * DK_];  // [B,S,H*DK]

// ---------------------------------------------------------------------------
// Kernel 1: fused QKV projection.
//   X[8192,1024] @ W[h][1024,64] + b[h]  ->  {Q,K,V}[B,H,S,DK]
// grid = (MROWS/128, H, 3), 256 threads, tile 128x64x32, micro-tile 8x4.
// ---------------------------------------------------------------------------
__global__ __launch_bounds__(256) void qkv_kernel(
    const float* __restrict__ x,
    const float* __restrict__ Wq, const float* __restrict__ bq,
    const float* __restrict__ Wk, const float* __restrict__ bk,
    const float* __restrict__ Wv, const float* __restrict__ bv)
{
    __shared__ float As[32][132];  // [k][m], pad 4 -> float4-aligned rows
    __shared__ float Bs[32][64];   // [k][n]

    const int type = blockIdx.z;
    const float* W    = (type == 0) ? Wq : (type == 1) ? Wk : Wv;
    const float* bias = (type == 0) ? bq : (type == 1) ? bk : bv;
    float* outp       = (type == 0) ? g_Q : (type == 1) ? g_K : g_V;

    const int h  = blockIdx.y;
    const int m0 = blockIdx.x * 128;
    const int tid = threadIdx.x;
    const int tm = tid >> 4;   // 0..15 (8 rows each)
    const int tn = tid & 15;   // 0..15 (4 cols each)

    const float* Wh = W + (size_t)h * D_ * DK_;

    float acc[8][4];
#pragma unroll
    for (int i = 0; i < 8; i++)
#pragma unroll
        for (int j = 0; j < 4; j++) acc[i][j] = 0.f;

    for (int k0 = 0; k0 < D_; k0 += 32) {
        // A tile: 128 rows x 32 k, stored transposed As[k][m]
#pragma unroll
        for (int L = 0; L < 4; L++) {
            int lin = tid + L * 256;          // 0..1023 float4 tasks
            int row = lin >> 3;               // 0..127
            int c4  = (lin & 7) * 4;          // 0..28
            float4 v = *(const float4*)(x + (size_t)(m0 + row) * D_ + k0 + c4);
            As[c4 + 0][row] = v.x;
            As[c4 + 1][row] = v.y;
            As[c4 + 2][row] = v.z;
            As[c4 + 3][row] = v.w;
        }
        // B tile: 32 k x 64 n
#pragma unroll
        for (int L = 0; L < 2; L++) {
            int lin = tid + L * 256;          // 0..511
            int row = lin >> 4;               // 0..31
            int c4  = (lin & 15) * 4;         // 0..60
            *(float4*)(&Bs[row][c4]) =
                *(const float4*)(Wh + (size_t)(k0 + row) * DK_ + c4);
        }
        __syncthreads();

#pragma unroll
        for (int k = 0; k < 32; k++) {
            float4 a0 = *(const float4*)(&As[k][tm * 8]);
            float4 a1 = *(const float4*)(&As[k][tm * 8 + 4]);
            float4 bb = *(const float4*)(&Bs[k][tn * 4]);
            float a[8] = {a0.x, a0.y, a0.z, a0.w, a1.x, a1.y, a1.z, a1.w};
            float b[4] = {bb.x, bb.y, bb.z, bb.w};
#pragma unroll
            for (int i = 0; i < 8; i++)
#pragma unroll
                for (int j = 0; j < 4; j++) acc[i][j] = fmaf(a[i], b[j], acc[i][j]);
        }
        __syncthreads();
    }

    float4 bb = *(const float4*)(bias + h * DK_ + tn * 4);
#pragma unroll
    for (int i = 0; i < 8; i++) {
        int rr = m0 + tm * 8 + i;
        int b  = rr >> 11;        // / 2048
        int s  = rr & 2047;
        float4 o;
        o.x = acc[i][0] + bb.x;
        o.y = acc[i][1] + bb.y;
        o.z = acc[i][2] + bb.z;
        o.w = acc[i][3] + bb.w;
        *(float4*)(outp + ((size_t)(b * H_ + h) * S_ + s) * DK_ + tn * 4) = o;
    }
}

// ---------------------------------------------------------------------------
// Kernel 2: flash attention (fp32, exact online softmax).
// grid = (S/64, B*H), 256 threads. Each block: 64 query rows of one (b,h).
// Streams KV in 64-row tiles; Q^T, K^T, V, P tiles in dynamic smem.
// Writes directly into concat layout g_cat[B,S,H*DK].
// ---------------------------------------------------------------------------
#define ATTN_SMEM_FLOATS (64 * 68 /*Qt*/ + 64 * 65 /*Kt*/ + 64 * 64 /*Vs*/ + 64 * 68 /*Ps*/ + 192)

__global__ __launch_bounds__(256) void attn_kernel()
{
    extern __shared__ float sm[];
    float* Qt   = sm;                  // [k=64][m=64]  stride 68 (float4 reads, bcast)
    float* Kt   = Qt + 64 * 68;        // [k=64][t=64]  stride 65 (scalar reads, conflict-free writes)
    float* Vs   = Kt + 64 * 65;        // [t=64][c=64]  stride 64
    float* Ps   = Vs + 64 * 64;        // [m=64][n/k=64] stride 68
    float* mrow = Ps + 64 * 68;        // [64]
    float* lrow = mrow + 64;           // [64]
    float* arow = lrow + 64;           // [64]

    const int bh = blockIdx.y;         // b*H + h
    const int q0 = blockIdx.x * 64;
    const float* Qg = g_Q + (size_t)bh * S_ * DK_;
    const float* Kg = g_K + (size_t)bh * S_ * DK_;
    const float* Vg = g_V + (size_t)bh * S_ * DK_;

    const int tid  = threadIdx.x;
    const int tm   = tid >> 4;   // 0..15 (4 rows)
    const int tn   = tid & 15;   // 0..15 (4 cols)
    const int lane = tid & 31;
    const int warp = tid >> 5;

    // Load Q tile transposed: Qt[k][m]
#pragma unroll
    for (int L = 0; L < 4; L++) {
        int lin = tid + L * 256;        // 0..1023
        int row = lin >> 4;             // 0..63 (query row)
        int c4  = (lin & 15) * 4;       // 0..60 (k)
        float4 v = *(const float4*)(Qg + (size_t)(q0 + row) * DK_ + c4);
        Qt[(c4 + 0) * 68 + row] = v.x;
        Qt[(c4 + 1) * 68 + row] = v.y;
        Qt[(c4 + 2) * 68 + row] = v.z;
        Qt[(c4 + 3) * 68 + row] = v.w;
    }
    if (tid < 64) { mrow[tid] = -INFINITY; lrow[tid] = 0.f; }

    float o[4][4];
#pragma unroll
    for (int i = 0; i < 4; i++)
#pragma unroll
        for (int j = 0; j < 4; j++) o[i][j] = 0.f;

    const float scale = 0.125f;  // 1/sqrt(64)

    for (int t0 = 0; t0 < S_; t0 += 64) {
        __syncthreads();  // previous iteration's readers of Kt/Vs are done

        // Load K tile transposed Kt[k][t] and V tile Vs[t][c]
#pragma unroll
        for (int L = 0; L < 4; L++) {
            int lin = tid + L * 256;
            int row = lin >> 4;          // t within tile
            int c4  = (lin & 15) * 4;    // channel
            float4 kv = *(const float4*)(Kg + (size_t)(t0 + row) * DK_ + c4);
            Kt[(c4 + 0) * 65 + row] = kv.x;
            Kt[(c4 + 1) * 65 + row] = kv.y;
            Kt[(c4 + 2) * 65 + row] = kv.z;
            Kt[(c4 + 3) * 65 + row] = kv.w;
            float4 vv = *(const float4*)(Vg + (size_t)(t0 + row) * DK_ + c4);
            *(float4*)(Vs + row * 64 + c4) = vv;
        }
        __syncthreads();

        // S tile: s[m][n] = sum_k Qt[k][m] * Kt[k][n]
        float s[4][4];
#pragma unroll
        for (int i = 0; i < 4; i++)
#pragma unroll
            for (int j = 0; j < 4; j++) s[i][j] = 0.f;

#pragma unroll 8
        for (int k = 0; k < 64; k++) {
            float4 aq = *(const float4*)(Qt + k * 68 + tm * 4);
            float b0 = Kt[k * 65 + tn * 4 + 0];
            float b1 = Kt[k * 65 + tn * 4 + 1];
            float b2 = Kt[k * 65 + tn * 4 + 2];
            float b3 = Kt[k * 65 + tn * 4 + 3];
            s[0][0] = fmaf(aq.x, b0, s[0][0]); s[0][1] = fmaf(aq.x, b1, s[0][1]);
            s[0][2] = fmaf(aq.x, b2, s[0][2]); s[0][3] = fmaf(aq.x, b3, s[0][3]);
            s[1][0] = fmaf(aq.y, b0, s[1][0]); s[1][1] = fmaf(aq.y, b1, s[1][1]);
            s[1][2] = fmaf(aq.y, b2, s[1][2]); s[1][3] = fmaf(aq.y, b3, s[1][3]);
            s[2][0] = fmaf(aq.z, b0, s[2][0]); s[2][1] = fmaf(aq.z, b1, s[2][1]);
            s[2][2] = fmaf(aq.z, b2, s[2][2]); s[2][3] = fmaf(aq.z, b3, s[2][3]);
            s[3][0] = fmaf(aq.w, b0, s[3][0]); s[3][1] = fmaf(aq.w, b1, s[3][1]);
            s[3][2] = fmaf(aq.w, b2, s[3][2]); s[3][3] = fmaf(aq.w, b3, s[3][3]);
        }
#pragma unroll
        for (int i = 0; i < 4; i++) {
            float4 w = make_float4(s[i][0] * scale, s[i][1] * scale,
                                   s[i][2] * scale, s[i][3] * scale);
            *(float4*)(Ps + (tm * 4 + i) * 68 + tn * 4) = w;
        }
        __syncthreads();

        // Online softmax: each warp owns 8 rows
#pragma unroll
        for (int r = 0; r < 8; r++) {
            int row = warp * 8 + r;
            float s1 = Ps[row * 68 + lane];
            float s2 = Ps[row * 68 + lane + 32];
            float mx = fmaxf(s1, s2);
#pragma unroll
            for (int off = 16; off > 0; off >>= 1)
                mx = fmaxf(mx, __shfl_xor_sync(0xffffffffu, mx, off));
            float mold = mrow[row];
            float mnew = fmaxf(mold, mx);
            float p1 = __expf(s1 - mnew);
            float p2 = __expf(s2 - mnew);
            float ps = p1 + p2;
#pragma unroll
            for (int off = 16; off > 0; off >>= 1)
                ps += __shfl_xor_sync(0xffffffffu, ps, off);
            if (lane == 0) {
                float al = __expf(mold - mnew);
                lrow[row] = lrow[row] * al + ps;
                mrow[row] = mnew;
                arow[row] = al;
            }
            Ps[row * 68 + lane]      = p1;
            Ps[row * 68 + lane + 32] = p2;
        }
        __syncthreads();

        // Rescale accumulators, then O += P @ V
        float al0 = arow[tm * 4 + 0];
        float al1 = arow[tm * 4 + 1];
        float al2 = arow[tm * 4 + 2];
        float al3 = arow[tm * 4 + 3];
#pragma unroll
        for (int j = 0; j < 4; j++) {
            o[0][j] *= al0; o[1][j] *= al1; o[2][j] *= al2; o[3][j] *= al3;
        }
#pragma unroll 8
        for (int k = 0; k < 64; k++) {
            float4 bv4 = *(const float4*)(Vs + k * 64 + tn * 4);
            float a0 = Ps[(tm * 4 + 0) * 68 + k];
            float a1 = Ps[(tm * 4 + 1) * 68 + k];
            float a2 = Ps[(tm * 4 + 2) * 68 + k];
            float a3 = Ps[(tm * 4 + 3) * 68 + k];
            o[0][0] = fmaf(a0, bv4.x, o[0][0]); o[0][1] = fmaf(a0, bv4.y, o[0][1]);
            o[0][2] = fmaf(a0, bv4.z, o[0][2]); o[0][3] = fmaf(a0, bv4.w, o[0][3]);
            o[1][0] = fmaf(a1, bv4.x, o[1][0]); o[1][1] = fmaf(a1, bv4.y, o[1][1]);
            o[1][2] = fmaf(a1, bv4.z, o[1][2]); o[1][3] = fmaf(a1, bv4.w, o[1][3]);
            o[2][0] = fmaf(a2, bv4.x, o[2][0]); o[2][1] = fmaf(a2, bv4.y, o[2][1]);
            o[2][2] = fmaf(a2, bv4.z, o[2][2]); o[2][3] = fmaf(a2, bv4.w, o[2][3]);
            o[3][0] = fmaf(a3, bv4.x, o[3][0]); o[3][1] = fmaf(a3, bv4.y, o[3][1]);
            o[3][2] = fmaf(a3, bv4.z, o[3][2]); o[3][3] = fmaf(a3, bv4.w, o[3][3]);
        }
    }

    // Finalize: divide by l, write into concat layout [B,S,H*DK]
    const int b = bh / H_;
    const int h = bh % H_;
#pragma unroll
    for (int i = 0; i < 4; i++) {
        int row = tm * 4 + i;
        float inv = 1.0f / lrow[row];
        float4 w = make_float4(o[i][0] * inv, o[i][1] * inv,
                               o[i][2] * inv, o[i][3] * inv);
        *(float4*)(g_cat + ((size_t)(b * S_ + q0 + row)) * (H_ * DK_)
                   + h * DK_ + tn * 4) = w;
    }
}

// ---------------------------------------------------------------------------
// Kernel 3: output projection. cat[8192,1024] @ Wo[1024,1024] + bo
// grid = (MROWS/128, DOUT/64), 256 threads, tile 128x64x32.
// ---------------------------------------------------------------------------
__global__ __launch_bounds__(256) void out_kernel(
    float* __restrict__ out,
    const float* __restrict__ Wo, const float* __restrict__ bo)
{
    __shared__ float As[32][132];
    __shared__ float Bs[32][64];

    const int m0 = blockIdx.x * 128;
    const int n0 = blockIdx.y * 64;
    const int tid = threadIdx.x;
    const int tm = tid >> 4;
    const int tn = tid & 15;

    float acc[8][4];
#pragma unroll
    for (int i = 0; i < 8; i++)
#pragma unroll
        for (int j = 0; j < 4; j++) acc[i][j] = 0.f;

    for (int k0 = 0; k0 < H_ * DK_; k0 += 32) {
#pragma unroll
        for (int L = 0; L < 4; L++) {
            int lin = tid + L * 256;
            int row = lin >> 3;
            int c4  = (lin & 7) * 4;
            float4 v = *(const float4*)(g_cat + (size_t)(m0 + row) * (H_ * DK_) + k0 + c4);
            As[c4 + 0][row] = v.x;
            As[c4 + 1][row] = v.y;
            As[c4 + 2][row] = v.z;
            As[c4 + 3][row] = v.w;
        }
#pragma unroll
        for (int L = 0; L < 2; L++) {
            int lin = tid + L * 256;
            int row = lin >> 4;
            int c4  = (lin & 15) * 4;
            *(float4*)(&Bs[row][c4]) =
                *(const float4*)(Wo + (size_t)(k0 + row) * DOUT_ + n0 + c4);
        }
        __syncthreads();

#pragma unroll
        for (int k = 0; k < 32; k++) {
            float4 a0 = *(const float4*)(&As[k][tm * 8]);
            float4 a1 = *(const float4*)(&As[k][tm * 8 + 4]);
            float4 bb = *(const float4*)(&Bs[k][tn * 4]);
            float a[8] = {a0.x, a0.y, a0.z, a0.w, a1.x, a1.y, a1.z, a1.w};
            float b[4] = {bb.x, bb.y, bb.z, bb.w};
#pragma unroll
            for (int i = 0; i < 8; i++)
#pragma unroll
                for (int j = 0; j < 4; j++) acc[i][j] = fmaf(a[i], b[j], acc[i][j]);
        }
        __syncthreads();
    }

    float4 bb = *(const float4*)(bo + n0 + tn * 4);
#pragma unroll
    for (int i = 0; i < 8; i++) {
        float4 o;
        o.x = acc[i][0] + bb.x;
        o.y = acc[i][1] + bb.y;
        o.z = acc[i][2] + bb.z;
        o.w = acc[i][3] + bb.w;
        *(float4*)(out + (size_t)(m0 + tm * 8 + i) * DOUT_ + n0 + tn * 4) = o;
    }
}

// ---------------------------------------------------------------------------
// Launch
// ---------------------------------------------------------------------------
extern "C" void kernel_launch(void* const* d_in, const int* in_sizes, int n_in,
                              void* d_out, int out_size)
{
    const float* x  = (const float*)d_in[0];
    const float* Wq = (const float*)d_in[1];
    const float* bq = (const float*)d_in[2];
    const float* Wk = (const float*)d_in[3];
    const float* bk = (const float*)d_in[4];
    const float* Wv = (const float*)d_in[5];
    const float* bv = (const float*)d_in[6];
    const float* Wo = (const float*)d_in[7];
    const float* bo = (const float*)d_in[8];
    float* out = (float*)d_out;

    const int attn_smem = ATTN_SMEM_FLOATS * (int)sizeof(float);  // ~68.6 KB
    cudaFuncSetAttribute(attn_kernel,
                         cudaFuncAttributeMaxDynamicSharedMemorySize, attn_smem);

    dim3 g1(MROWS / 128, H_, 3);
    qkv_kernel<<<g1, 256>>>(x, Wq, bq, Wk, bk, Wv, bv);

    dim3 g2(S_ / 64, B_ * H_);
    attn_kernel<<<g2, 256, attn_smem>>>();

    dim3 g3(MROWS / 128, DOUT_ / 64);
    out_kernel<<<g3, 256>>>(out, Wo, bo);
}

// round 2
// speedup vs baseline: 3.3463x; 3.3463x over previous
#include <cuda_runtime.h>
#include <math.h>
#include <stdint.h>

// Problem constants
#define B_    4
#define S_    2048
#define D_    1024
#define H_    16
#define DK_   64
#define DOUT_ 1024
#define MROWS (B_ * S_)   // 8192

// Scratch (no allocation allowed in kernel_launch)
__device__ float g_Q[(size_t)B_ * H_ * S_ * DK_];    // [B,H,S,DK]
__device__ float g_K[(size_t)B_ * H_ * S_ * DK_];
__device__ float g_V[(size_t)B_ * H_ * S_ * DK_];
__device__ float g_cat[(size_t)B_ * S_ * H_ * DK_];  // [B,S,H*DK]

// ---------------------------------------------------------------------------
// Helpers: fp32 -> tf32 (round-to-nearest), m16n8k8 tf32 MMA
// ---------------------------------------------------------------------------
__device__ __forceinline__ uint32_t f2tf(float f) {
    uint32_t u;
    asm("cvt.rna.tf32.f32 %0, %1;" : "=r"(u) : "f"(f));
    return u;
}

__device__ __forceinline__ void mma_tf32(float* d,
                                         uint32_t a0, uint32_t a1, uint32_t a2, uint32_t a3,
                                         uint32_t b0, uint32_t b1) {
    asm volatile(
        "mma.sync.aligned.m16n8k8.row.col.f32.tf32.tf32.f32 "
        "{%0,%1,%2,%3}, {%4,%5,%6,%7}, {%8,%9}, {%0,%1,%2,%3};"
        : "+f"(d[0]), "+f"(d[1]), "+f"(d[2]), "+f"(d[3])
        : "r"(a0), "r"(a1), "r"(a2), "r"(a3), "r"(b0), "r"(b1));
}

// ---------------------------------------------------------------------------
// Kernel 1: fused QKV projection via tf32 MMA.
//   X[8192,1024] @ W[h][1024,64] + b[h]  ->  {Q,K,V}[B,H,S,DK]
// grid = (64, 16, 3), 256 threads (8 warps), block tile 128x64, warp tile 32x32.
// ---------------------------------------------------------------------------
#define XS_STR 36
#define WS_STR 72

__global__ __launch_bounds__(256) void qkv_mma_kernel(
    const float* __restrict__ x,
    const float* __restrict__ Wq, const float* __restrict__ bq,
    const float* __restrict__ Wk, const float* __restrict__ bk,
    const float* __restrict__ Wv, const float* __restrict__ bv)
{
    __shared__ uint32_t Xs[128 * XS_STR];  // [m][k], K-chunk 32
    __shared__ uint32_t Ws[32 * WS_STR];   // [k][n] natural, B col-major reads

    const int type = blockIdx.z;
    const float* W    = (type == 0) ? Wq : (type == 1) ? Wk : Wv;
    const float* bias = (type == 0) ? bq : (type == 1) ? bk : bv;
    float* outp       = (type == 0) ? g_Q : (type == 1) ? g_K : g_V;

    const int h  = blockIdx.y;
    const int m0 = blockIdx.x * 128;
    const int tid  = threadIdx.x;
    const int warp = tid >> 5;
    const int lane = tid & 31;
    const int gid  = lane >> 2;    // 0..7
    const int t4   = lane & 3;     // 0..3
    const int wm   = warp >> 1;    // 0..3 -> 32 M-rows each
    const int wn   = warp & 1;     // 0..1 -> 32 N-cols each

    const float* Wh = W + (size_t)h * D_ * DK_;

    float acc[2][4][4];
#pragma unroll
    for (int mt = 0; mt < 2; mt++)
#pragma unroll
        for (int nt = 0; nt < 4; nt++)
#pragma unroll
            for (int j = 0; j < 4; j++) acc[mt][nt][j] = 0.f;

    for (int k0 = 0; k0 < D_; k0 += 32) {
        // X tile [128 x 32]
#pragma unroll
        for (int L = 0; L < 4; L++) {
            int lin = tid + L * 256;
            int row = lin >> 3;
            int c4  = (lin & 7) * 4;
            float4 v = *(const float4*)(x + (size_t)(m0 + row) * D_ + k0 + c4);
            Xs[row * XS_STR + c4 + 0] = f2tf(v.x);
            Xs[row * XS_STR + c4 + 1] = f2tf(v.y);
            Xs[row * XS_STR + c4 + 2] = f2tf(v.z);
            Xs[row * XS_STR + c4 + 3] = f2tf(v.w);
        }
        // W tile [32 x 64], natural [k][n]
#pragma unroll
        for (int L = 0; L < 2; L++) {
            int lin = tid + L * 256;
            int kr = lin >> 4;
            int n4 = (lin & 15) * 4;
            float4 w = *(const float4*)(Wh + (size_t)(k0 + kr) * DK_ + n4);
            Ws[kr * WS_STR + n4 + 0] = f2tf(w.x);
            Ws[kr * WS_STR + n4 + 1] = f2tf(w.y);
            Ws[kr * WS_STR + n4 + 2] = f2tf(w.z);
            Ws[kr * WS_STR + n4 + 3] = f2tf(w.w);
        }
        __syncthreads();

#pragma unroll
        for (int ks = 0; ks < 4; ks++) {
            uint32_t b[4][2];
#pragma unroll
            for (int nt = 0; nt < 4; nt++) {
                int n = wn * 32 + nt * 8 + gid;
                b[nt][0] = Ws[(ks * 8 + t4)     * WS_STR + n];
                b[nt][1] = Ws[(ks * 8 + t4 + 4) * WS_STR + n];
            }
#pragma unroll
            for (int mt = 0; mt < 2; mt++) {
                int rb = wm * 32 + mt * 16;
                uint32_t a0 = Xs[(rb + gid)     * XS_STR + ks * 8 + t4];
                uint32_t a1 = Xs[(rb + gid + 8) * XS_STR + ks * 8 + t4];
                uint32_t a2 = Xs[(rb + gid)     * XS_STR + ks * 8 + t4 + 4];
                uint32_t a3 = Xs[(rb + gid + 8) * XS_STR + ks * 8 + t4 + 4];
#pragma unroll
                for (int nt = 0; nt < 4; nt++)
                    mma_tf32(acc[mt][nt], a0, a1, a2, a3, b[nt][0], b[nt][1]);
            }
        }
        __syncthreads();
    }

    // Epilogue: bias + store to [B,H,S,DK]
#pragma unroll
    for (int nt = 0; nt < 4; nt++) {
        int bcol = wn * 32 + nt * 8 + 2 * t4;
        float bb0 = bias[h * DK_ + bcol];
        float bb1 = bias[h * DK_ + bcol + 1];
#pragma unroll
        for (int mt = 0; mt < 2; mt++) {
#pragma unroll
            for (int half = 0; half < 2; half++) {
                int gm = m0 + wm * 32 + mt * 16 + gid + half * 8;
                int bb = gm >> 11;
                int s  = gm & 2047;
                float2 o;
                o.x = acc[mt][nt][half * 2 + 0] + bb0;
                o.y = acc[mt][nt][half * 2 + 1] + bb1;
                *(float2*)(outp + ((size_t)(bb * H_ + h) * S_ + s) * DK_ + bcol) = o;
            }
        }
    }
}

// ---------------------------------------------------------------------------
// Kernel 2: flash attention, tf32 MMA + register-resident online softmax.
// grid = (S/128, B*H), 256 threads (8 warps). Warp owns 16 query rows.
// KV streamed in 64-row tiles. Row stats (m,l) live in registers of the
// 4 lanes sharing groupID; reductions via shfl_xor(1),shfl_xor(2).
// ---------------------------------------------------------------------------
#define QS_STR 68
#define KS_STR 68
#define VS_STR 72
#define PS_STR 68
#define ATTN_SMEM_WORDS (128 * QS_STR + 64 * KS_STR + 64 * VS_STR + 128 * PS_STR)

__global__ __launch_bounds__(256, 2) void attn_mma_kernel()
{
    extern __shared__ uint32_t smw[];
    uint32_t* Qs = smw;                    // [q=128][c] tf32
    uint32_t* Ks = Qs + 128 * QS_STR;      // [t=64][c]  tf32 (natural)
    uint32_t* Vs = Ks + 64 * KS_STR;       // [t=64][c]  tf32 (natural)
    uint32_t* Ps = Vs + 64 * VS_STR;       // [q=128][t] tf32

    const int bh = blockIdx.y;
    const int q0 = blockIdx.x * 128;
    const float* Qg = g_Q + (size_t)bh * S_ * DK_;
    const float* Kg = g_K + (size_t)bh * S_ * DK_;
    const float* Vg = g_V + (size_t)bh * S_ * DK_;

    const int tid  = threadIdx.x;
    const int warp = tid >> 5;
    const int lane = tid & 31;
    const int gid  = lane >> 2;
    const int t4   = lane & 3;
    const int w16  = warp * 16;

    // Load Q tile [128 x 64] -> tf32
#pragma unroll
    for (int L = 0; L < 8; L++) {
        int lin = tid + L * 256;
        int row = lin >> 4;
        int c4  = (lin & 15) * 4;
        float4 v = *(const float4*)(Qg + (size_t)(q0 + row) * DK_ + c4);
        Qs[row * QS_STR + c4 + 0] = f2tf(v.x);
        Qs[row * QS_STR + c4 + 1] = f2tf(v.y);
        Qs[row * QS_STR + c4 + 2] = f2tf(v.z);
        Qs[row * QS_STR + c4 + 3] = f2tf(v.w);
    }

    float o[8][4];
#pragma unroll
    for (int nt = 0; nt < 8; nt++)
#pragma unroll
        for (int j = 0; j < 4; j++) o[nt][j] = 0.f;
    float m0r = -1e30f, m1r = -1e30f, l0r = 0.f, l1r = 0.f;
    const float scale = 0.125f;  // 1/sqrt(64)

    for (int t0 = 0; t0 < S_; t0 += 64) {
        __syncthreads();  // all warps done with previous K/V tiles
        // Load K,V tiles [64 x 64] natural layout
#pragma unroll
        for (int L = 0; L < 4; L++) {
            int lin = tid + L * 256;
            int row = lin >> 4;
            int c4  = (lin & 15) * 4;
            float4 kv = *(const float4*)(Kg + (size_t)(t0 + row) * DK_ + c4);
            Ks[row * KS_STR + c4 + 0] = f2tf(kv.x);
            Ks[row * KS_STR + c4 + 1] = f2tf(kv.y);
            Ks[row * KS_STR + c4 + 2] = f2tf(kv.z);
            Ks[row * KS_STR + c4 + 3] = f2tf(kv.w);
            float4 vv = *(const float4*)(Vg + (size_t)(t0 + row) * DK_ + c4);
            Vs[row * VS_STR + c4 + 0] = f2tf(vv.x);
            Vs[row * VS_STR + c4 + 1] = f2tf(vv.y);
            Vs[row * VS_STR + c4 + 2] = f2tf(vv.z);
            Vs[row * VS_STR + c4 + 3] = f2tf(vv.w);
        }
        __syncthreads();

        // ---- S = Q @ K^T  (warp: 16 q-rows x 64 t-cols) ----
        float s[8][4];
#pragma unroll
        for (int nt = 0; nt < 8; nt++)
#pragma unroll
            for (int j = 0; j < 4; j++) s[nt][j] = 0.f;

#pragma unroll
        for (int ks = 0; ks < 8; ks++) {
            uint32_t a0 = Qs[(w16 + gid)     * QS_STR + ks * 8 + t4];
            uint32_t a1 = Qs[(w16 + gid + 8) * QS_STR + ks * 8 + t4];
            uint32_t a2 = Qs[(w16 + gid)     * QS_STR + ks * 8 + t4 + 4];
            uint32_t a3 = Qs[(w16 + gid + 8) * QS_STR + ks * 8 + t4 + 4];
#pragma unroll
            for (int nt = 0; nt < 8; nt++) {
                uint32_t b0 = Ks[(nt * 8 + gid) * KS_STR + ks * 8 + t4];
                uint32_t b1 = Ks[(nt * 8 + gid) * KS_STR + ks * 8 + t4 + 4];
                mma_tf32(s[nt], a0, a1, a2, a3, b0, b1);
            }
        }

        // ---- online softmax (rows r0 = w16+gid, r1 = w16+gid+8) ----
        float rm0 = -1e30f, rm1 = -1e30f;
#pragma unroll
        for (int nt = 0; nt < 8; nt++) {
            rm0 = fmaxf(rm0, fmaxf(s[nt][0], s[nt][1]));
            rm1 = fmaxf(rm1, fmaxf(s[nt][2], s[nt][3]));
        }
        rm0 *= scale; rm1 *= scale;
        rm0 = fmaxf(rm0, __shfl_xor_sync(0xffffffffu, rm0, 1));
        rm0 = fmaxf(rm0, __shfl_xor_sync(0xffffffffu, rm0, 2));
        rm1 = fmaxf(rm1, __shfl_xor_sync(0xffffffffu, rm1, 1));
        rm1 = fmaxf(rm1, __shfl_xor_sync(0xffffffffu, rm1, 2));

        float mn0 = fmaxf(m0r, rm0);
        float mn1 = fmaxf(m1r, rm1);
        float al0 = __expf(m0r - mn0);
        float al1 = __expf(m1r - mn1);
        m0r = mn0; m1r = mn1;

        float sum0 = 0.f, sum1 = 0.f;
#pragma unroll
        for (int nt = 0; nt < 8; nt++) {
            float p0 = __expf(s[nt][0] * scale - mn0);
            float p1 = __expf(s[nt][1] * scale - mn0);
            float p2 = __expf(s[nt][2] * scale - mn1);
            float p3 = __expf(s[nt][3] * scale - mn1);
            sum0 += p0 + p1; sum1 += p2 + p3;
            // store P (warp-private rows of Ps; no block sync needed)
            int col = nt * 8 + 2 * t4;
            Ps[(w16 + gid)     * PS_STR + col]     = f2tf(p0);
            Ps[(w16 + gid)     * PS_STR + col + 1] = f2tf(p1);
            Ps[(w16 + gid + 8) * PS_STR + col]     = f2tf(p2);
            Ps[(w16 + gid + 8) * PS_STR + col + 1] = f2tf(p3);
        }
        sum0 += __shfl_xor_sync(0xffffffffu, sum0, 1);
        sum0 += __shfl_xor_sync(0xffffffffu, sum0, 2);
        sum1 += __shfl_xor_sync(0xffffffffu, sum1, 1);
        sum1 += __shfl_xor_sync(0xffffffffu, sum1, 2);
        l0r = l0r * al0 + sum0;
        l1r = l1r * al1 + sum1;

        // rescale O accumulators
#pragma unroll
        for (int nt = 0; nt < 8; nt++) {
            o[nt][0] *= al0; o[nt][1] *= al0;
            o[nt][2] *= al1; o[nt][3] *= al1;
        }

        // ---- O += P @ V  (warp: 16 q-rows x 64 channels) ----
#pragma unroll
        for (int ks = 0; ks < 8; ks++) {
            uint32_t a0 = Ps[(w16 + gid)     * PS_STR + ks * 8 + t4];
            uint32_t a1 = Ps[(w16 + gid + 8) * PS_STR + ks * 8 + t4];
            uint32_t a2 = Ps[(w16 + gid)     * PS_STR + ks * 8 + t4 + 4];
            uint32_t a3 = Ps[(w16 + gid + 8) * PS_STR + ks * 8 + t4 + 4];
#pragma unroll
            for (int nt = 0; nt < 8; nt++) {
                uint32_t b0 = Vs[(ks * 8 + t4)     * VS_STR + nt * 8 + gid];
                uint32_t b1 = Vs[(ks * 8 + t4 + 4) * VS_STR + nt * 8 + gid];
                mma_tf32(o[nt], a0, a1, a2, a3, b0, b1);
            }
        }
    }

    // Finalize: divide by l, write concat layout [B,S,H*DK]
    const int b = bh / H_;
    const int h = bh % H_;
    float inv0 = 1.0f / l0r;
    float inv1 = 1.0f / l1r;
#pragma unroll
    for (int nt = 0; nt < 8; nt++) {
        int col = nt * 8 + 2 * t4;
        int r0 = q0 + w16 + gid;
        int r1 = r0 + 8;
        float2 w0 = make_float2(o[nt][0] * inv0, o[nt][1] * inv0);
        float2 w1 = make_float2(o[nt][2] * inv1, o[nt][3] * inv1);
        *(float2*)(g_cat + ((size_t)(b * S_ + r0)) * (H_ * DK_) + h * DK_ + col) = w0;
        *(float2*)(g_cat + ((size_t)(b * S_ + r1)) * (H_ * DK_) + h * DK_ + col) = w1;
    }
}

// ---------------------------------------------------------------------------
// Kernel 3: output projection via tf32 MMA. cat[8192,1024] @ Wo[1024,1024]+bo
// grid = (64, 16), 256 threads, block tile 128x64.
// ---------------------------------------------------------------------------
__global__ __launch_bounds__(256) void out_mma_kernel(
    float* __restrict__ out,
    const float* __restrict__ Wo, const float* __restrict__ bo)
{
    __shared__ uint32_t Xs[128 * XS_STR];
    __shared__ uint32_t Ws[32 * WS_STR];

    const int m0 = blockIdx.x * 128;
    const int n0 = blockIdx.y * 64;
    const int tid  = threadIdx.x;
    const int warp = tid >> 5;
    const int lane = tid & 31;
    const int gid  = lane >> 2;
    const int t4   = lane & 3;
    const int wm   = warp >> 1;
    const int wn   = warp & 1;

    float acc[2][4][4];
#pragma unroll
    for (int mt = 0; mt < 2; mt++)
#pragma unroll
        for (int nt = 0; nt < 4; nt++)
#pragma unroll
            for (int j = 0; j < 4; j++) acc[mt][nt][j] = 0.f;

    for (int k0 = 0; k0 < H_ * DK_; k0 += 32) {
#pragma unroll
        for (int L = 0; L < 4; L++) {
            int lin = tid + L * 256;
            int row = lin >> 3;
            int c4  = (lin & 7) * 4;
            float4 v = *(const float4*)(g_cat + (size_t)(m0 + row) * (H_ * DK_) + k0 + c4);
            Xs[row * XS_STR + c4 + 0] = f2tf(v.x);
            Xs[row * XS_STR + c4 + 1] = f2tf(v.y);
            Xs[row * XS_STR + c4 + 2] = f2tf(v.z);
            Xs[row * XS_STR + c4 + 3] = f2tf(v.w);
        }
#pragma unroll
        for (int L = 0; L < 2; L++) {
            int lin = tid + L * 256;
            int kr = lin >> 4;
            int n4 = (lin & 15) * 4;
            float4 w = *(const float4*)(Wo + (size_t)(k0 + kr) * DOUT_ + n0 + n4);
            Ws[kr * WS_STR + n4 + 0] = f2tf(w.x);
            Ws[kr * WS_STR + n4 + 1] = f2tf(w.y);
            Ws[kr * WS_STR + n4 + 2] = f2tf(w.z);
            Ws[kr * WS_STR + n4 + 3] = f2tf(w.w);
        }
        __syncthreads();

#pragma unroll
        for (int ks = 0; ks < 4; ks++) {
            uint32_t b[4][2];
#pragma unroll
            for (int nt = 0; nt < 4; nt++) {
                int n = wn * 32 + nt * 8 + gid;
                b[nt][0] = Ws[(ks * 8 + t4)     * WS_STR + n];
                b[nt][1] = Ws[(ks * 8 + t4 + 4) * WS_STR + n];
            }
#pragma unroll
            for (int mt = 0; mt < 2; mt++) {
                int rb = wm * 32 + mt * 16;
                uint32_t a0 = Xs[(rb + gid)     * XS_STR + ks * 8 + t4];
                uint32_t a1 = Xs[(rb + gid + 8) * XS_STR + ks * 8 + t4];
                uint32_t a2 = Xs[(rb + gid)     * XS_STR + ks * 8 + t4 + 4];
                uint32_t a3 = Xs[(rb + gid + 8) * XS_STR + ks * 8 + t4 + 4];
#pragma unroll
                for (int nt = 0; nt < 4; nt++)
                    mma_tf32(acc[mt][nt], a0, a1, a2, a3, b[nt][0], b[nt][1]);
            }
        }
        __syncthreads();
    }

#pragma unroll
    for (int nt = 0; nt < 4; nt++) {
        int ncol = n0 + wn * 32 + nt * 8 + 2 * t4;
        float bb0 = bo[ncol];
        float bb1 = bo[ncol + 1];
#pragma unroll
        for (int mt = 0; mt < 2; mt++) {
#pragma unroll
            for (int half = 0; half < 2; half++) {
                int gm = m0 + wm * 32 + mt * 16 + gid + half * 8;
                float2 o;
                o.x = acc[mt][nt][half * 2 + 0] + bb0;
                o.y = acc[mt][nt][half * 2 + 1] + bb1;
                *(float2*)(out + (size_t)gm * DOUT_ + ncol) = o;
            }
        }
    }
}

// ---------------------------------------------------------------------------
// Launch
// ---------------------------------------------------------------------------
extern "C" void kernel_launch(void* const* d_in, const int* in_sizes, int n_in,
                              void* d_out, int out_size)
{
    const float* x  = (const float*)d_in[0];
    const float* Wq = (const float*)d_in[1];
    const float* bq = (const float*)d_in[2];
    const float* Wk = (const float*)d_in[3];
    const float* bk = (const float*)d_in[4];
    const float* Wv = (const float*)d_in[5];
    const float* bv = (const float*)d_in[6];
    const float* Wo = (const float*)d_in[7];
    const float* bo = (const float*)d_in[8];
    float* out = (float*)d_out;

    const int attn_smem = ATTN_SMEM_WORDS * (int)sizeof(uint32_t);  // ~103 KB
    cudaFuncSetAttribute(attn_mma_kernel,
                         cudaFuncAttributeMaxDynamicSharedMemorySize, attn_smem);

    dim3 g1(MROWS / 128, H_, 3);
    qkv_mma_kernel<<<g1, 256>>>(x, Wq, bq, Wk, bk, Wv, bv);

    dim3 g2(S_ / 128, B_ * H_);
    attn_mma_kernel<<<g2, 256, attn_smem>>>();

    dim3 g3(MROWS / 128, DOUT_ / 64);
    out_mma_kernel<<<g3, 256>>>(out, Wo, bo);
}